// round 2
// baseline (speedup 1.0000x reference)
#include <cuda_runtime.h>
#include <math.h>

#define NE 3200000
#define NN 100000
#define EPT 4   // edges per thread in edge kernel

// ---------------- loop-invariant device state ----------------
__device__ float g_W1[16*5];
__device__ float g_b1[16];
__device__ float g_W2[32*16];
__device__ float g_b2[32];
__device__ float g_W3[16*35];
__device__ float g_b3[16];
__device__ float g_W4[16];
__device__ float g_b4[1];

__device__ int   g_src[NE];
__device__ int   g_dst[NE];
__device__ float g_x0[NN];
__device__ float g_x1[NN];
__device__ float g_x2[NN];
__device__ unsigned g_agg[NN * 32];   // float bits; all stored values >= 0
__device__ int   g_is_i32;            // 1 if edge_index buffer is int32, 0 if int64

__device__ __forceinline__ float softplusf(float v) {
    return (v > 20.f) ? v : log1pf(expf(v));
}

// ---------------- detect edge_index element width ----------------
// If int64: odd 32-bit words are high words of values < NN -> all zero.
// If int32: odd words are random node ids -> nonzero almost surely.
__global__ void detect_layout(const unsigned* __restrict__ ei_words)
{
    int t = blockIdx.x * blockDim.x + threadIdx.x;
    if (t == 0) g_is_i32 = 0;   // overwritten below if evidence found (race-free enough:
                                // we instead use a two-kernel-free approach via atomics)
}

__global__ void detect_layout2(const unsigned* __restrict__ ei_words)
{
    int t = blockIdx.x * blockDim.x + threadIdx.x;
    if (t < 100000) {
        if (ei_words[2*t + 1] != 0u) atomicExch(&g_is_i32, 1);
    }
}

// ---------------- prep: sample Bayesian weights once ----------------
__global__ void prep_weights(
    const float* w1m, const float* w1r, const float* b1m, const float* b1r, const float* e1w, const float* e1b,
    const float* w2m, const float* w2r, const float* b2m, const float* b2r, const float* e2w, const float* e2b,
    const float* w3m, const float* w3r, const float* b3m, const float* b3r, const float* e3w, const float* e3b,
    const float* w4m, const float* w4r, const float* b4m, const float* b4r, const float* e4w, const float* e4b)
{
    int t = blockIdx.x * blockDim.x + threadIdx.x;
    int stride = gridDim.x * blockDim.x;
    for (int i = t; i < 16*5;  i += stride) g_W1[i] = w1m[i] + softplusf(w1r[i]) * e1w[i];
    for (int i = t; i < 16;    i += stride) g_b1[i] = b1m[i] + softplusf(b1r[i]) * e1b[i];
    for (int i = t; i < 32*16; i += stride) g_W2[i] = w2m[i] + softplusf(w2r[i]) * e2w[i];
    for (int i = t; i < 32;    i += stride) g_b2[i] = b2m[i] + softplusf(b2r[i]) * e2b[i];
    for (int i = t; i < 16*35; i += stride) g_W3[i] = w3m[i] + softplusf(w3r[i]) * e3w[i];
    for (int i = t; i < 16;    i += stride) g_b3[i] = b3m[i] + softplusf(b3r[i]) * e3b[i];
    for (int i = t; i < 16;    i += stride) g_W4[i] = w4m[i] + softplusf(w4r[i]) * e4w[i];
    for (int i = t; i < 1;     i += stride) g_b4[i] = b4m[i] + softplusf(b4r[i]) * e4b[i];
}

// ---------------- prep: edge index -> int32 planes (handles i32 or i64) ----------------
__global__ void prep_edges(const int* __restrict__ ei)
{
    int e = blockIdx.x * blockDim.x + threadIdx.x;
    if (e >= NE) return;
    int s, d;
    if (g_is_i32) {
        s = ei[e];
        d = ei[NE + e];
    } else {
        s = ei[2*e];            // little-endian low word of int64
        d = ei[2*(NE + e)];
    }
    // defensive clamp: wrong layout guess -> bad values, not IMA
    if ((unsigned)s >= NN) s = 0;
    if ((unsigned)d >= NN) d = 0;
    g_src[e] = s;
    g_dst[e] = d;
}

// ---------------- prep: x AoS -> SoA planes ----------------
__global__ void prep_x(const float* __restrict__ x)
{
    int i = blockIdx.x * blockDim.x + threadIdx.x;
    if (i < NN) {
        g_x0[i] = x[3*i + 0];
        g_x1[i] = x[3*i + 1];
        g_x2[i] = x[3*i + 2];
    }
}

// ---------------- zero agg (12.8 MB, vectorized) ----------------
__global__ void zero_agg()
{
    int i = blockIdx.x * blockDim.x + threadIdx.x;   // NN*32/4 = 800000 uint4s
    uint4* p = reinterpret_cast<uint4*>(g_agg);
    if (i < (NN * 32) / 4) p[i] = make_uint4(0u, 0u, 0u, 0u);
}

// ---------------- edge MLP + segment-max scatter ----------------
__global__ void __launch_bounds__(256) edge_kernel(const float2* __restrict__ ea)
{
    __shared__ float sW1[16*5], sb1[16], sW2[32*16], sb2[32];
    for (int i = threadIdx.x; i < 16*5;  i += blockDim.x) sW1[i] = g_W1[i];
    for (int i = threadIdx.x; i < 16;    i += blockDim.x) sb1[i] = g_b1[i];
    for (int i = threadIdx.x; i < 32*16; i += blockDim.x) sW2[i] = g_W2[i];
    for (int i = threadIdx.x; i < 32;    i += blockDim.x) sb2[i] = g_b2[i];
    __syncthreads();

    // coalesced: thread t of block b handles edges b*blockDim*EPT + i*blockDim + t
    int base = blockIdx.x * blockDim.x * EPT + threadIdx.x;

    int   dsts[EPT];
    float m1[EPT][16];

    #pragma unroll
    for (int i = 0; i < EPT; i++) {
        int e = base + i * blockDim.x;
        int s = g_src[e];
        dsts[i] = g_dst[e];
        float x0 = g_x0[s];
        float x1 = g_x1[s];
        float x2 = g_x2[s];
        float2 a = ea[e];
        #pragma unroll
        for (int j = 0; j < 16; j++) {
            float v = sb1[j];
            v = fmaf(sW1[j*5 + 0], x0,  v);
            v = fmaf(sW1[j*5 + 1], x1,  v);
            v = fmaf(sW1[j*5 + 2], x2,  v);
            v = fmaf(sW1[j*5 + 3], a.x, v);
            v = fmaf(sW1[j*5 + 4], a.y, v);
            m1[i][j] = fmaxf(v, 0.f);
        }
    }

    #pragma unroll
    for (int j = 0; j < 32; j++) {
        float acc[EPT];
        float bj = sb2[j];
        #pragma unroll
        for (int i = 0; i < EPT; i++) acc[i] = bj;
        #pragma unroll
        for (int k = 0; k < 16; k++) {
            float w = sW2[j*16 + k];
            #pragma unroll
            for (int i = 0; i < EPT; i++) acc[i] = fmaf(w, m1[i][k], acc[i]);
        }
        #pragma unroll
        for (int i = 0; i < EPT; i++) {
            float r = fmaxf(acc[i], 0.f);
            unsigned bits = __float_as_uint(r);
            // agg starts at 0; skip atomics for ReLU zeros (bits==0)
            if (bits) atomicMax(&g_agg[(unsigned)dsts[i] * 32u + j], bits);
        }
    }
}

// ---------------- node MLP: [x, agg] -> 16 -> sigmoid ----------------
__global__ void __launch_bounds__(256) node_kernel(float* __restrict__ out, int last)
{
    __shared__ float sW3[16*35], sb3[16], sW4[16], sb4[1];
    for (int i = threadIdx.x; i < 16*35; i += blockDim.x) sW3[i] = g_W3[i];
    for (int i = threadIdx.x; i < 16;    i += blockDim.x) sb3[i] = g_b3[i];
    for (int i = threadIdx.x; i < 16;    i += blockDim.x) sW4[i] = g_W4[i];
    if (threadIdx.x == 0) sb4[0] = g_b4[0];
    __syncthreads();

    int i = blockIdx.x * blockDim.x + threadIdx.x;
    if (i >= NN) return;

    float h[35];
    h[0] = g_x0[i];
    h[1] = g_x1[i];
    h[2] = g_x2[i];
    const uint4* ar = reinterpret_cast<const uint4*>(g_agg + (size_t)i * 32);
    #pragma unroll
    for (int q = 0; q < 8; q++) {
        uint4 v = ar[q];
        h[3 + 4*q + 0] = __uint_as_float(v.x);
        h[3 + 4*q + 1] = __uint_as_float(v.y);
        h[3 + 4*q + 2] = __uint_as_float(v.z);
        h[3 + 4*q + 3] = __uint_as_float(v.w);
    }

    float t[16];
    #pragma unroll
    for (int j = 0; j < 16; j++) {
        float s = sb3[j];
        #pragma unroll
        for (int k = 0; k < 35; k++) s = fmaf(sW3[j*35 + k], h[k], s);
        t[j] = fmaxf(s, 0.f);
    }

    float z = sb4[0];
    #pragma unroll
    for (int k = 0; k < 16; k++) z = fmaf(sW4[k], t[k], z);

    float comb = 1.f / (1.f + expf(-z));
    g_x2[i] = comb;

    if (last) {
        out[3*i + 0] = h[0];
        out[3*i + 1] = h[1];
        out[3*i + 2] = comb;
    }
}

// ---------------- launch ----------------
extern "C" void kernel_launch(void* const* d_in, const int* in_sizes, int n_in,
                              void* d_out, int out_size)
{
    const float* x  = (const float*)d_in[0];
    const float* ea = (const float*)d_in[1];
    const void*  ei = d_in[2];
    const float* P[24];
    for (int i = 0; i < 24; i++) P[i] = (const float*)d_in[3 + i];

    detect_layout<<<1, 32>>>((const unsigned*)ei);            // reset flag
    detect_layout2<<<(100000 + 255) / 256, 256>>>((const unsigned*)ei);

    prep_weights<<<4, 256>>>(
        P[0],  P[1],  P[2],  P[3],  P[4],  P[5],
        P[6],  P[7],  P[8],  P[9],  P[10], P[11],
        P[12], P[13], P[14], P[15], P[16], P[17],
        P[18], P[19], P[20], P[21], P[22], P[23]);

    prep_edges<<<(NE + 255) / 256, 256>>>((const int*)ei);
    prep_x<<<(NN + 255) / 256, 256>>>(x);

    const int edge_blocks = NE / (256 * EPT);          // 3125, exact
    const int node_blocks = (NN + 255) / 256;          // 391
    const int zero_blocks = ((NN * 32) / 4 + 255) / 256;

    for (int it = 0; it < 3; it++) {
        zero_agg<<<zero_blocks, 256>>>();
        edge_kernel<<<edge_blocks, 256>>>((const float2*)ea);
        node_kernel<<<node_blocks, 256>>>((float*)d_out, it == 2 ? 1 : 0);
    }
}

// round 3
// speedup vs baseline: 1.6414x; 1.6414x over previous
#include <cuda_runtime.h>
#include <cuda_fp16.h>
#include <math.h>

#define NE 3200000
#define NN 100000
#define EPT 4
#define SCAN_T 512
#define SCAN_NB 196   // 196*512 = 100352 >= NN

// ---------------- loop-invariant device state ----------------
__device__ float g_W1[16*5];
__device__ float g_b1[16];
__device__ float g_W2[32*16];
__device__ float g_b2[32];
__device__ float g_W3[16*35];
__device__ float g_b3[16];
__device__ float g_W4[16];
__device__ float g_b4[1];

__device__ int    g_src[NE];
__device__ int    g_dst[NE];
__device__ int    g_ssrc[NE];       // dst-sorted src
__device__ float2 g_sea[NE];        // dst-sorted edge_attr
__device__ int    g_cnt[NN];
__device__ int    g_off[NN + 1];
__device__ int    g_pos[NN];
__device__ int    g_bsum[SCAN_NB];
__device__ int    g_bpre[SCAN_NB];

__device__ float4   g_xp[NN];       // (x0, x1, x2, unused)
__device__ unsigned g_m2[(size_t)NE * 16];   // per-edge 32 fp16 features (16 half2)
__device__ unsigned g_aggh[NN * 16];         // per-node 32 fp16 agg (16 half2)
__device__ int      g_is_i32;

__device__ __forceinline__ float softplusf(float v) {
    return (v > 20.f) ? v : log1pf(expf(v));
}

__device__ __forceinline__ unsigned hmax2_bits(unsigned a, unsigned b) {
    __half2 ha = *reinterpret_cast<__half2*>(&a);
    __half2 hb = *reinterpret_cast<__half2*>(&b);
    __half2 r = __hmax2(ha, hb);
    return *reinterpret_cast<unsigned*>(&r);
}

// ---------------- detect edge_index element width ----------------
__global__ void detect_reset() { g_is_i32 = 0; }

__global__ void detect_layout(const unsigned* __restrict__ ei_words)
{
    int t = blockIdx.x * blockDim.x + threadIdx.x;
    if (t < 100000) {
        if (ei_words[2*t + 1] != 0u) atomicExch(&g_is_i32, 1);
    }
}

// ---------------- prep: sample Bayesian weights ----------------
__global__ void prep_weights(
    const float* w1m, const float* w1r, const float* b1m, const float* b1r, const float* e1w, const float* e1b,
    const float* w2m, const float* w2r, const float* b2m, const float* b2r, const float* e2w, const float* e2b,
    const float* w3m, const float* w3r, const float* b3m, const float* b3r, const float* e3w, const float* e3b,
    const float* w4m, const float* w4r, const float* b4m, const float* b4r, const float* e4w, const float* e4b)
{
    int t = blockIdx.x * blockDim.x + threadIdx.x;
    int stride = gridDim.x * blockDim.x;
    for (int i = t; i < 16*5;  i += stride) g_W1[i] = w1m[i] + softplusf(w1r[i]) * e1w[i];
    for (int i = t; i < 16;    i += stride) g_b1[i] = b1m[i] + softplusf(b1r[i]) * e1b[i];
    for (int i = t; i < 32*16; i += stride) g_W2[i] = w2m[i] + softplusf(w2r[i]) * e2w[i];
    for (int i = t; i < 32;    i += stride) g_b2[i] = b2m[i] + softplusf(b2r[i]) * e2b[i];
    for (int i = t; i < 16*35; i += stride) g_W3[i] = w3m[i] + softplusf(w3r[i]) * e3w[i];
    for (int i = t; i < 16;    i += stride) g_b3[i] = b3m[i] + softplusf(b3r[i]) * e3b[i];
    for (int i = t; i < 16;    i += stride) g_W4[i] = w4m[i] + softplusf(w4r[i]) * e4w[i];
    for (int i = t; i < 1;     i += stride) g_b4[i] = b4m[i] + softplusf(b4r[i]) * e4b[i];
}

// ---------------- prep: edge index -> int32 planes + zero histogram ----------------
__global__ void prep_edges(const int* __restrict__ ei)
{
    int e = blockIdx.x * blockDim.x + threadIdx.x;
    if (e >= NE) return;
    int s, d;
    if (g_is_i32) { s = ei[e];   d = ei[NE + e]; }
    else          { s = ei[2*e]; d = ei[2*(NE + e)]; }
    if ((unsigned)s >= NN) s = 0;
    if ((unsigned)d >= NN) d = 0;
    g_src[e] = s;
    g_dst[e] = d;
    if (e < NN) g_cnt[e] = 0;
}

// ---------------- prep: x -> float4 ----------------
__global__ void prep_x(const float* __restrict__ x)
{
    int i = blockIdx.x * blockDim.x + threadIdx.x;
    if (i < NN) g_xp[i] = make_float4(x[3*i + 0], x[3*i + 1], x[3*i + 2], 0.f);
}

// ---------------- sort step 1: histogram ----------------
__global__ void hist_kernel()
{
    int e = blockIdx.x * blockDim.x + threadIdx.x;
    if (e < NE) atomicAdd(&g_cnt[g_dst[e]], 1);
}

// ---------------- sort step 2: block-level exclusive scan ----------------
__global__ void scan_blocks()
{
    __shared__ int s[SCAN_T];
    int t = threadIdx.x;
    int i = blockIdx.x * SCAN_T + t;
    int v = (i < NN) ? g_cnt[i] : 0;
    s[t] = v;
    __syncthreads();
    for (int off = 1; off < SCAN_T; off <<= 1) {
        int x = (t >= off) ? s[t - off] : 0;
        __syncthreads();
        s[t] += x;
        __syncthreads();
    }
    if (i < NN) g_off[i] = s[t] - v;          // exclusive within block
    if (t == SCAN_T - 1) g_bsum[blockIdx.x] = s[t];
}

// ---------------- sort step 3: scan of block sums (1 block) ----------------
__global__ void scan_sums()
{
    __shared__ int s[256];
    int t = threadIdx.x;
    int v = (t < SCAN_NB) ? g_bsum[t] : 0;
    s[t] = v;
    __syncthreads();
    for (int off = 1; off < 256; off <<= 1) {
        int x = (t >= off) ? s[t - off] : 0;
        __syncthreads();
        s[t] += x;
        __syncthreads();
    }
    if (t < SCAN_NB) g_bpre[t] = s[t] - v;    // exclusive
}

// ---------------- sort step 4: add block prefixes, init cursors ----------------
__global__ void scan_fixup()
{
    int i = blockIdx.x * blockDim.x + threadIdx.x;
    if (i < NN) {
        int o = g_off[i] + g_bpre[i / SCAN_T];
        g_off[i] = o;
        g_pos[i] = o;
    }
    if (i == 0) g_off[NN] = NE;
}

// ---------------- sort step 5: scatter src / edge_attr into sorted order ----------------
__global__ void scatter_kernel(const float2* __restrict__ ea)
{
    int e = blockIdx.x * blockDim.x + threadIdx.x;
    if (e >= NE) return;
    int d = g_dst[e];
    int p = atomicAdd(&g_pos[d], 1);
    g_ssrc[p] = g_src[e];
    g_sea[p]  = ea[e];
}

// ---------------- edge MLP over sorted edges -> fp16 m2 ----------------
__global__ void __launch_bounds__(256) edge_kernel()
{
    __shared__ float sW1[16*5], sb1[16], sW2[32*16], sb2[32];
    for (int i = threadIdx.x; i < 16*5;  i += blockDim.x) sW1[i] = g_W1[i];
    for (int i = threadIdx.x; i < 16;    i += blockDim.x) sb1[i] = g_b1[i];
    for (int i = threadIdx.x; i < 32*16; i += blockDim.x) sW2[i] = g_W2[i];
    for (int i = threadIdx.x; i < 32;    i += blockDim.x) sb2[i] = g_b2[i];
    __syncthreads();

    int base = blockIdx.x * blockDim.x * EPT + threadIdx.x;

    float m1[EPT][16];
    unsigned buf[EPT][16];

    #pragma unroll
    for (int i = 0; i < EPT; i++) {
        int e = base + i * blockDim.x;
        int s = g_ssrc[e];
        float4 xv = g_xp[s];
        float2 a  = g_sea[e];
        #pragma unroll
        for (int j = 0; j < 16; j++) {
            float v = sb1[j];
            v = fmaf(sW1[j*5 + 0], xv.x, v);
            v = fmaf(sW1[j*5 + 1], xv.y, v);
            v = fmaf(sW1[j*5 + 2], xv.z, v);
            v = fmaf(sW1[j*5 + 3], a.x,  v);
            v = fmaf(sW1[j*5 + 4], a.y,  v);
            m1[i][j] = fmaxf(v, 0.f);
        }
    }

    #pragma unroll
    for (int jp = 0; jp < 16; jp++) {
        int j0 = 2*jp, j1 = 2*jp + 1;
        float a0[EPT], a1[EPT];
        float b0 = sb2[j0], b1 = sb2[j1];
        #pragma unroll
        for (int i = 0; i < EPT; i++) { a0[i] = b0; a1[i] = b1; }
        #pragma unroll
        for (int k = 0; k < 16; k++) {
            float w0 = sW2[j0*16 + k];
            float w1 = sW2[j1*16 + k];
            #pragma unroll
            for (int i = 0; i < EPT; i++) {
                a0[i] = fmaf(w0, m1[i][k], a0[i]);
                a1[i] = fmaf(w1, m1[i][k], a1[i]);
            }
        }
        #pragma unroll
        for (int i = 0; i < EPT; i++) {
            __half2 h = __floats2half2_rn(fmaxf(a0[i], 0.f), fmaxf(a1[i], 0.f));
            buf[i][jp] = *reinterpret_cast<unsigned*>(&h);
        }
    }

    #pragma unroll
    for (int i = 0; i < EPT; i++) {
        int e = base + i * blockDim.x;
        uint4* dst = reinterpret_cast<uint4*>(&g_m2[(size_t)e * 16]);
        const uint4* srcb = reinterpret_cast<const uint4*>(buf[i]);
        dst[0] = srcb[0]; dst[1] = srcb[1]; dst[2] = srcb[2]; dst[3] = srcb[3];
    }
}

// ---------------- segment max: warp per node, no atomics ----------------
__global__ void __launch_bounds__(256) agg_kernel()
{
    int warp = (blockIdx.x * blockDim.x + threadIdx.x) >> 5;
    int lane = threadIdx.x & 31;
    if (warp >= NN) return;

    int start = g_off[warp];
    int end   = g_off[warp + 1];

    unsigned run = 0;   // half2(0, 0)
    // half-warp h handles edges start+2i+h; lane&15 selects the half2 feature pair
    for (int e = start + (lane >> 4); e < end; e += 2) {
        unsigned v = g_m2[(size_t)e * 16 + (lane & 15)];
        run = hmax2_bits(run, v);
    }
    run = hmax2_bits(run, __shfl_xor_sync(0xffffffffu, run, 16));
    if (lane < 16) g_aggh[warp * 16 + lane] = run;
}

// ---------------- node MLP ----------------
__global__ void __launch_bounds__(256) node_kernel(float* __restrict__ out, int last)
{
    __shared__ float sW3[16*35], sb3[16], sW4[16], sb4[1];
    for (int i = threadIdx.x; i < 16*35; i += blockDim.x) sW3[i] = g_W3[i];
    for (int i = threadIdx.x; i < 16;    i += blockDim.x) sb3[i] = g_b3[i];
    for (int i = threadIdx.x; i < 16;    i += blockDim.x) sW4[i] = g_W4[i];
    if (threadIdx.x == 0) sb4[0] = g_b4[0];
    __syncthreads();

    int i = blockIdx.x * blockDim.x + threadIdx.x;
    if (i >= NN) return;

    float4 xv = g_xp[i];
    float h[35];
    h[0] = xv.x; h[1] = xv.y; h[2] = xv.z;

    const uint4* ar = reinterpret_cast<const uint4*>(&g_aggh[i * 16]);
    #pragma unroll
    for (int q = 0; q < 4; q++) {
        uint4 v = ar[q];
        unsigned ws[4] = {v.x, v.y, v.z, v.w};
        #pragma unroll
        for (int p = 0; p < 4; p++) {
            float2 f = __half22float2(*reinterpret_cast<__half2*>(&ws[p]));
            h[3 + q*8 + 2*p + 0] = f.x;
            h[3 + q*8 + 2*p + 1] = f.y;
        }
    }

    float t[16];
    #pragma unroll
    for (int j = 0; j < 16; j++) {
        float s = sb3[j];
        #pragma unroll
        for (int k = 0; k < 35; k++) s = fmaf(sW3[j*35 + k], h[k], s);
        t[j] = fmaxf(s, 0.f);
    }

    float z = sb4[0];
    #pragma unroll
    for (int k = 0; k < 16; k++) z = fmaf(sW4[k], t[k], z);

    float comb = 1.f / (1.f + expf(-z));
    reinterpret_cast<float*>(&g_xp[i])[2] = comb;   // update x2 plane

    if (last) {
        out[3*i + 0] = xv.x;
        out[3*i + 1] = xv.y;
        out[3*i + 2] = comb;
    }
}

// ---------------- launch ----------------
extern "C" void kernel_launch(void* const* d_in, const int* in_sizes, int n_in,
                              void* d_out, int out_size)
{
    const float* x  = (const float*)d_in[0];
    const float* ea = (const float*)d_in[1];
    const void*  ei = d_in[2];
    const float* P[24];
    for (int i = 0; i < 24; i++) P[i] = (const float*)d_in[3 + i];

    detect_reset<<<1, 32>>>();
    detect_layout<<<(100000 + 255) / 256, 256>>>((const unsigned*)ei);

    prep_weights<<<4, 256>>>(
        P[0],  P[1],  P[2],  P[3],  P[4],  P[5],
        P[6],  P[7],  P[8],  P[9],  P[10], P[11],
        P[12], P[13], P[14], P[15], P[16], P[17],
        P[18], P[19], P[20], P[21], P[22], P[23]);

    prep_edges<<<(NE + 255) / 256, 256>>>((const int*)ei);
    prep_x<<<(NN + 255) / 256, 256>>>(x);

    // counting sort by dst (per replay; max is order-independent within segments)
    hist_kernel<<<(NE + 255) / 256, 256>>>();
    scan_blocks<<<SCAN_NB, SCAN_T>>>();
    scan_sums<<<1, 256>>>();
    scan_fixup<<<(NN + 255) / 256, 256>>>();
    scatter_kernel<<<(NE + 255) / 256, 256>>>((const float2*)ea);

    const int edge_blocks = NE / (256 * EPT);           // 3125, exact
    const int node_blocks = (NN + 255) / 256;           // 391
    const int agg_blocks  = (NN * 32 + 255) / 256;      // 12500 (warp per node)

    for (int it = 0; it < 3; it++) {
        edge_kernel<<<edge_blocks, 256>>>();
        agg_kernel<<<agg_blocks, 256>>>();
        node_kernel<<<node_blocks, 256>>>((float*)d_out, it == 2 ? 1 : 0);
    }
}

// round 4
// speedup vs baseline: 2.3228x; 1.4151x over previous
#include <cuda_runtime.h>
#include <cuda_fp16.h>
#include <math.h>

#define NE 3200000
#define NN 100000
#define SCAN_T 512
#define SCAN_NB 196   // 196*512 = 100352 >= NN

// ---------------- device state ----------------
__device__ float g_W1[16*5];
__device__ float g_b1[16];
__device__ float g_W2[32*16];
__device__ float g_b2[32];
__device__ float g_W3[16*35];
__device__ float g_b3[16];
__device__ float g_W4[16];
__device__ float g_b4[1];

__device__ int    g_src[NE];
__device__ int    g_dst[NE];
__device__ int4   g_sedge[NE];      // dst-sorted {src, dst, ea.x bits, ea.y bits}
__device__ int    g_cnt[NN];
__device__ int    g_off[NN + 1];
__device__ int    g_pos[NN];
__device__ int    g_bsum[SCAN_NB];
__device__ int    g_bpre[SCAN_NB];

__device__ float4   g_xp[NN];       // (x0, x1, x2, unused)
__device__ unsigned g_agg[NN * 32]; // fp32 bit patterns, all values >= 0
__device__ int      g_is_i32;

__device__ __forceinline__ float softplusf(float v) {
    return (v > 20.f) ? v : log1pf(expf(v));
}

__device__ __forceinline__ unsigned hmax2_bits(unsigned a, unsigned b) {
    __half2 ha = *reinterpret_cast<__half2*>(&a);
    __half2 hb = *reinterpret_cast<__half2*>(&b);
    __half2 r = __hmax2(ha, hb);
    return *reinterpret_cast<unsigned*>(&r);
}

// ---------------- detect edge_index width + zero histogram ----------------
__global__ void detect_reset() { g_is_i32 = 0; }

__global__ void detect_layout(const unsigned* __restrict__ ei_words)
{
    int t = blockIdx.x * blockDim.x + threadIdx.x;
    if (t < 100000) {
        if (ei_words[2*t + 1] != 0u) atomicExch(&g_is_i32, 1);
        g_cnt[t] = 0;   // NN == 100000
    }
}

// ---------------- prep: sample Bayesian weights ----------------
__global__ void prep_weights(
    const float* w1m, const float* w1r, const float* b1m, const float* b1r, const float* e1w, const float* e1b,
    const float* w2m, const float* w2r, const float* b2m, const float* b2r, const float* e2w, const float* e2b,
    const float* w3m, const float* w3r, const float* b3m, const float* b3r, const float* e3w, const float* e3b,
    const float* w4m, const float* w4r, const float* b4m, const float* b4r, const float* e4w, const float* e4b)
{
    int t = blockIdx.x * blockDim.x + threadIdx.x;
    int stride = gridDim.x * blockDim.x;
    for (int i = t; i < 16*5;  i += stride) g_W1[i] = w1m[i] + softplusf(w1r[i]) * e1w[i];
    for (int i = t; i < 16;    i += stride) g_b1[i] = b1m[i] + softplusf(b1r[i]) * e1b[i];
    for (int i = t; i < 32*16; i += stride) g_W2[i] = w2m[i] + softplusf(w2r[i]) * e2w[i];
    for (int i = t; i < 32;    i += stride) g_b2[i] = b2m[i] + softplusf(b2r[i]) * e2b[i];
    for (int i = t; i < 16*35; i += stride) g_W3[i] = w3m[i] + softplusf(w3r[i]) * e3w[i];
    for (int i = t; i < 16;    i += stride) g_b3[i] = b3m[i] + softplusf(b3r[i]) * e3b[i];
    for (int i = t; i < 16;    i += stride) g_W4[i] = w4m[i] + softplusf(w4r[i]) * e4w[i];
    for (int i = t; i < 1;     i += stride) g_b4[i] = b4m[i] + softplusf(b4r[i]) * e4b[i];
}

// ---------------- prep: edge index -> planes + histogram ----------------
__global__ void prep_edges(const int* __restrict__ ei)
{
    int e = blockIdx.x * blockDim.x + threadIdx.x;
    if (e >= NE) return;
    int s, d;
    if (g_is_i32) { s = ei[e];   d = ei[NE + e]; }
    else          { s = ei[2*e]; d = ei[2*(NE + e)]; }
    if ((unsigned)s >= NN) s = 0;
    if ((unsigned)d >= NN) d = 0;
    g_src[e] = s;
    g_dst[e] = d;
    atomicAdd(&g_cnt[d], 1);
}

// ---------------- prep: x -> float4 ----------------
__global__ void prep_x(const float* __restrict__ x)
{
    int i = blockIdx.x * blockDim.x + threadIdx.x;
    if (i < NN) g_xp[i] = make_float4(x[3*i + 0], x[3*i + 1], x[3*i + 2], 0.f);
}

// ---------------- scan: block-level exclusive ----------------
__global__ void scan_blocks()
{
    __shared__ int s[SCAN_T];
    int t = threadIdx.x;
    int i = blockIdx.x * SCAN_T + t;
    int v = (i < NN) ? g_cnt[i] : 0;
    s[t] = v;
    __syncthreads();
    for (int off = 1; off < SCAN_T; off <<= 1) {
        int x = (t >= off) ? s[t - off] : 0;
        __syncthreads();
        s[t] += x;
        __syncthreads();
    }
    if (i < NN) g_off[i] = s[t] - v;
    if (t == SCAN_T - 1) g_bsum[blockIdx.x] = s[t];
}

__global__ void scan_sums()
{
    __shared__ int s[256];
    int t = threadIdx.x;
    int v = (t < SCAN_NB) ? g_bsum[t] : 0;
    s[t] = v;
    __syncthreads();
    for (int off = 1; off < 256; off <<= 1) {
        int x = (t >= off) ? s[t - off] : 0;
        __syncthreads();
        s[t] += x;
        __syncthreads();
    }
    if (t < SCAN_NB) g_bpre[t] = s[t] - v;
}

__global__ void scan_fixup()
{
    int i = blockIdx.x * blockDim.x + threadIdx.x;
    if (i < NN) g_pos[i] = g_off[i] + g_bpre[i / SCAN_T];
}

// ---------------- scatter: sorted edge records ----------------
__global__ void scatter_kernel(const float2* __restrict__ ea)
{
    int e = blockIdx.x * blockDim.x + threadIdx.x;
    if (e >= NE) return;
    int d = g_dst[e];
    int p = atomicAdd(&g_pos[d], 1);
    float2 a = ea[e];
    g_sedge[p] = make_int4(g_src[e], d, __float_as_int(a.x), __float_as_int(a.y));
}

// ---------------- zero agg ----------------
__global__ void zero_agg()
{
    int i = blockIdx.x * blockDim.x + threadIdx.x;   // NN*32/4 uint4s
    uint4* p = reinterpret_cast<uint4*>(g_agg);
    if (i < (NN * 32) / 4) p[i] = make_uint4(0u, 0u, 0u, 0u);
}

// ---------------- fused edge MLP + warp-segmented max ----------------
__global__ void __launch_bounds__(256) edge_fused_kernel()
{
    __shared__ float    sW1[16*5], sb1[16];
    __shared__ unsigned sW2h[16*16];   // half2(W2[2jp][k], W2[2jp+1][k]) at [k*16+jp]
    __shared__ unsigned sb2h[16];

    for (int i = threadIdx.x; i < 16*5; i += blockDim.x) sW1[i] = g_W1[i];
    for (int i = threadIdx.x; i < 16;   i += blockDim.x) sb1[i] = g_b1[i];
    for (int i = threadIdx.x; i < 256;  i += blockDim.x) {
        int k = i >> 4, jp = i & 15;
        __half2 h = __floats2half2_rn(g_W2[(2*jp)*16 + k], g_W2[(2*jp+1)*16 + k]);
        sW2h[i] = *reinterpret_cast<unsigned*>(&h);
    }
    for (int i = threadIdx.x; i < 16; i += blockDim.x) {
        __half2 h = __floats2half2_rn(g_b2[2*i], g_b2[2*i+1]);
        sb2h[i] = *reinterpret_cast<unsigned*>(&h);
    }
    __syncthreads();

    int lane = threadIdx.x & 31;
    int e = blockIdx.x * blockDim.x + threadIdx.x;   // consecutive sorted edges per warp

    int4 rec = g_sedge[e];
    int s   = rec.x;
    int dst = rec.y;
    float ax = __int_as_float(rec.z);
    float ay = __int_as_float(rec.w);
    float4 xv = g_xp[s];

    // layer 1 (fp32)
    float m1[16];
    #pragma unroll
    for (int j = 0; j < 16; j++) {
        float v = sb1[j];
        v = fmaf(sW1[j*5 + 0], xv.x, v);
        v = fmaf(sW1[j*5 + 1], xv.y, v);
        v = fmaf(sW1[j*5 + 2], xv.z, v);
        v = fmaf(sW1[j*5 + 3], ax,   v);
        v = fmaf(sW1[j*5 + 4], ay,   v);
        m1[j] = fmaxf(v, 0.f);
    }

    // layer 2 (half2 over output pairs) + ReLU
    unsigned acc[16];
    #pragma unroll
    for (int jp = 0; jp < 16; jp++) acc[jp] = sb2h[jp];
    #pragma unroll
    for (int k = 0; k < 16; k++) {
        __half2 mb = __half2half2(__float2half(m1[k]));
        #pragma unroll
        for (int jp = 0; jp < 16; jp++) {
            __half2 w = *reinterpret_cast<__half2*>(&sW2h[k*16 + jp]);
            __half2 a = *reinterpret_cast<__half2*>(&acc[jp]);
            a = __hfma2(w, mb, a);
            acc[jp] = *reinterpret_cast<unsigned*>(&a);
        }
    }
    #pragma unroll
    for (int jp = 0; jp < 16; jp++) acc[jp] = hmax2_bits(acc[jp], 0u);

    // warp-segmented suffix max keyed on dst (edges sorted by dst)
    #pragma unroll
    for (int s2 = 1; s2 < 32; s2 <<= 1) {
        int dn = __shfl_down_sync(0xffffffffu, dst, s2);
        bool take = (lane + s2 < 32) && (dn == dst);
        #pragma unroll
        for (int q = 0; q < 16; q++) {
            unsigned o = __shfl_down_sync(0xffffffffu, acc[q], q == 0 ? s2 : s2);
            if (take) acc[q] = hmax2_bits(acc[q], o);
        }
    }

    int dprev = __shfl_up_sync(0xffffffffu, dst, 1);
    bool head = (lane == 0) || (dprev != dst);
    if (head) {
        unsigned* base = &g_agg[(unsigned)dst * 32u];
        #pragma unroll
        for (int q = 0; q < 16; q++) {
            float2 f = __half22float2(*reinterpret_cast<__half2*>(&acc[q]));
            unsigned b0 = __float_as_uint(f.x);
            unsigned b1 = __float_as_uint(f.y);
            if (b0) atomicMax(&base[2*q],     b0);
            if (b1) atomicMax(&base[2*q + 1], b1);
        }
    }
}

// ---------------- node MLP ----------------
__global__ void __launch_bounds__(256) node_kernel(float* __restrict__ out, int last)
{
    __shared__ float sW3[16*35], sb3[16], sW4[16], sb4[1];
    for (int i = threadIdx.x; i < 16*35; i += blockDim.x) sW3[i] = g_W3[i];
    for (int i = threadIdx.x; i < 16;    i += blockDim.x) sb3[i] = g_b3[i];
    for (int i = threadIdx.x; i < 16;    i += blockDim.x) sW4[i] = g_W4[i];
    if (threadIdx.x == 0) sb4[0] = g_b4[0];
    __syncthreads();

    int i = blockIdx.x * blockDim.x + threadIdx.x;
    if (i >= NN) return;

    float4 xv = g_xp[i];
    float h[35];
    h[0] = xv.x; h[1] = xv.y; h[2] = xv.z;

    const uint4* ar = reinterpret_cast<const uint4*>(&g_agg[(size_t)i * 32]);
    #pragma unroll
    for (int q = 0; q < 8; q++) {
        uint4 v = ar[q];
        h[3 + 4*q + 0] = __uint_as_float(v.x);
        h[3 + 4*q + 1] = __uint_as_float(v.y);
        h[3 + 4*q + 2] = __uint_as_float(v.z);
        h[3 + 4*q + 3] = __uint_as_float(v.w);
    }

    float t[16];
    #pragma unroll
    for (int j = 0; j < 16; j++) {
        float s = sb3[j];
        #pragma unroll
        for (int k = 0; k < 35; k++) s = fmaf(sW3[j*35 + k], h[k], s);
        t[j] = fmaxf(s, 0.f);
    }

    float z = sb4[0];
    #pragma unroll
    for (int k = 0; k < 16; k++) z = fmaf(sW4[k], t[k], z);

    float comb = 1.f / (1.f + expf(-z));
    reinterpret_cast<float*>(&g_xp[i])[2] = comb;

    if (last) {
        out[3*i + 0] = xv.x;
        out[3*i + 1] = xv.y;
        out[3*i + 2] = comb;
    }
}

// ---------------- launch ----------------
extern "C" void kernel_launch(void* const* d_in, const int* in_sizes, int n_in,
                              void* d_out, int out_size)
{
    const float* x  = (const float*)d_in[0];
    const float* ea = (const float*)d_in[1];
    const void*  ei = d_in[2];
    const float* P[24];
    for (int i = 0; i < 24; i++) P[i] = (const float*)d_in[3 + i];

    detect_reset<<<1, 32>>>();
    detect_layout<<<(100000 + 255) / 256, 256>>>((const unsigned*)ei);

    prep_weights<<<4, 256>>>(
        P[0],  P[1],  P[2],  P[3],  P[4],  P[5],
        P[6],  P[7],  P[8],  P[9],  P[10], P[11],
        P[12], P[13], P[14], P[15], P[16], P[17],
        P[18], P[19], P[20], P[21], P[22], P[23]);

    prep_edges<<<(NE + 255) / 256, 256>>>((const int*)ei);
    prep_x<<<(NN + 255) / 256, 256>>>(x);

    scan_blocks<<<SCAN_NB, SCAN_T>>>();
    scan_sums<<<1, 256>>>();
    scan_fixup<<<(NN + 255) / 256, 256>>>();
    scatter_kernel<<<(NE + 255) / 256, 256>>>((const float2*)ea);

    const int edge_blocks = NE / 256;               // 12500
    const int node_blocks = (NN + 255) / 256;       // 391
    const int zero_blocks = ((NN * 32) / 4 + 255) / 256;

    for (int it = 0; it < 3; it++) {
        zero_agg<<<zero_blocks, 256>>>();
        edge_fused_kernel<<<edge_blocks, 256>>>();
        node_kernel<<<node_blocks, 256>>>((float*)d_out, it == 2 ? 1 : 0);
    }
}